// round 15
// baseline (speedup 1.0000x reference)
#include <cuda_runtime.h>
#include <cstdint>

#define HD  128
#define BBZ 512
#define LL  1000
#define NB  16
#define CLN 4
#define NTHREADS 512
#define KSTR 130                 // row stride (2 mod 32 -> conflict-free LDS.64)

#define OFF_W1 0
#define OFF_W2 16640
#define OFF_W3 33280
#define OFF_H1 49920             // [2][16][128]
#define OFF_H2 54016             // [2][16][128]
#define SMEM_FLOATS 58112
#define SMEM_BYTES (SMEM_FLOATS * 4)

typedef unsigned long long u64t;

__device__ __forceinline__ float sigf(float v) {
    return __fdividef(1.f, 1.f + __expf(-v));
}
__device__ __forceinline__ float tanhf_fast(float v) {
    float a = fabsf(v);
    float e = __expf(-2.f * a);
    return copysignf(__fdividef(1.f - e, 1.f + e), v);
}
__device__ __forceinline__ void cluster_bar() {
    asm volatile("barrier.cluster.arrive.aligned;" ::: "memory");
    asm volatile("barrier.cluster.wait.aligned;" ::: "memory");
}
__device__ __forceinline__ void ffma2(u64t& d, u64t a, u64t b) {
    asm("fma.rn.f32x2 %0, %1, %2, %0;" : "+l"(d) : "l"(a), "l"(b));
}
__device__ __forceinline__ float hadd2(u64t d) {
    float lo, hi;
    asm("mov.b64 {%0, %1}, %2;" : "=f"(lo), "=f"(hi) : "l"(d));
    return lo + hi;
}
__device__ __forceinline__ void st_cluster(uint32_t a, float v) {
    asm volatile("st.shared::cluster.f32 [%0], %1;" :: "r"(a), "f"(v) : "memory");
}

__global__ void __launch_bounds__(NTHREADS, 1) __cluster_dims__(CLN, 1, 1)
lstm_persistent_kernel(const float* __restrict__ x,
                       const float* __restrict__ w_ih1,
                       const float* __restrict__ w_hh1,
                       const float* __restrict__ b_ih1,
                       const float* __restrict__ b_hh1,
                       const float* __restrict__ w_ih2,
                       const float* __restrict__ w_hh2,
                       const float* __restrict__ b_ih2,
                       const float* __restrict__ b_hh2,
                       const float* __restrict__ w_lin,
                       const float* __restrict__ b_lin,
                       float* __restrict__ out)
{
    extern __shared__ float sm[];
    const int tid = threadIdx.x;
    uint32_t rank;
    asm("mov.u32 %0, %%cluster_ctarank;" : "=r"(rank));
    const int cid = blockIdx.x / CLN;
    const int batch0 = cid * NB;

    // ---- init: weight slices [gate][unit][k], stride KSTR ----
    for (int idx = tid; idx < 4 * 32 * HD; idx += NTHREADS) {
        int g = idx >> 12, u5 = (idx >> 7) & 31, k = idx & 127;
        int R = g * HD + (int)rank * 32 + u5;
        int o = (g * 32 + u5) * KSTR + k;
        sm[OFF_W1 + o] = w_hh1[R * HD + k];
        sm[OFF_W2 + o] = w_ih2[R * HD + k];
        sm[OFF_W3 + o] = w_hh2[R * HD + k];
    }
    for (int idx = tid; idx < 4096; idx += NTHREADS) {
        sm[OFF_H1 + idx] = 0.f;
        sm[OFF_H2 + idx] = 0.f;
    }

    // warp roles: gp = gate pair, bg = batch group (4 batches), ks = k half
    const int u  = tid & 31;
    const int w  = tid >> 5;          // 0..15
    const int gp = w & 1;
    const int bg = (w >> 1) & 3;
    const int ks = w >> 3;
    const int b0 = bg * 4;
    const int gu = (int)rank * 32 + u;
    const int kbase = ks * 64;
    const int owned = b0 + ks * 2 + gp;   // each warp owns exactly 1 batch

    const float wi0 = w_ih1[0 * HD + gu], wi1 = w_ih1[1 * HD + gu];
    const float wi2 = w_ih1[2 * HD + gu], wi3 = w_ih1[3 * HD + gu];
    const float bA0 = b_ih1[0 * HD + gu] + b_hh1[0 * HD + gu];
    const float bA1 = b_ih1[1 * HD + gu] + b_hh1[1 * HD + gu];
    const float bA2 = b_ih1[2 * HD + gu] + b_hh1[2 * HD + gu];
    const float bA3 = b_ih1[3 * HD + gu] + b_hh1[3 * HD + gu];
    const float bB0 = b_ih2[0 * HD + gu] + b_hh2[0 * HD + gu];
    const float bB1 = b_ih2[1 * HD + gu] + b_hh2[1 * HD + gu];
    const float bB2 = b_ih2[2 * HD + gu] + b_hh2[2 * HD + gu];
    const float bB3 = b_ih2[3 * HD + gu] + b_hh2[3 * HD + gu];
    const float wl0 = w_lin[u], wl1 = w_lin[u + 32];
    const float wl2 = w_lin[u + 64], wl3 = w_lin[u + 96];
    const float blin = b_lin[0];

    float c1 = 0.f, c2 = 0.f;

    const uint32_t sbase = (uint32_t)__cvta_generic_to_shared(sm);
    uint32_t peer[CLN];
#pragma unroll
    for (int r = 0; r < CLN; r++)
        asm("mapa.shared::cluster.u32 %0, %1, %2;" : "=r"(peer[r]) : "r"(sbase), "r"(r));

    // weight row pointers for this warp's 2 gates (8B aligned: KSTR*u + kbase even)
    const u64t* w1A = (const u64t*)(sm + OFF_W1 + ((2 * gp + 0) * 32 + u) * KSTR + kbase);
    const u64t* w1B = (const u64t*)(sm + OFF_W1 + ((2 * gp + 1) * 32 + u) * KSTR + kbase);
    const u64t* w2A = (const u64t*)(sm + OFF_W2 + ((2 * gp + 0) * 32 + u) * KSTR + kbase);
    const u64t* w2B = (const u64t*)(sm + OFF_W2 + ((2 * gp + 1) * 32 + u) * KSTR + kbase);
    const u64t* w3A = (const u64t*)(sm + OFF_W3 + ((2 * gp + 0) * 32 + u) * KSTR + kbase);
    const u64t* w3B = (const u64t*)(sm + OFF_W3 + ((2 * gp + 1) * 32 + u) * KSTR + kbase);
    const size_t xrow = (size_t)(batch0 + owned) * LL;

    __syncthreads();
    cluster_bar();   // weights + zeroed h visible cluster-wide

    for (int t = 0; t < LL; ++t) {
        const int pbuf = t & 1, qbuf = pbuf ^ 1;
        const float xv = x[xrow + t];

        // ========= layer 1 matvec: Whh1 @ h1[qbuf] (2 gates, 4 batches, 64 k) =========
        u64t acc[2][4];
#pragma unroll
        for (int g = 0; g < 2; g++)
#pragma unroll
            for (int b = 0; b < 4; b++) acc[g][b] = 0ULL;
        {
            const ulonglong2* hq =
                (const ulonglong2*)(sm + OFF_H1 + qbuf * 2048 + b0 * 128 + kbase);
#pragma unroll 4
            for (int i = 0; i < 16; ++i) {
                u64t wa0 = w1A[2 * i], wa1 = w1A[2 * i + 1];
                u64t wb0 = w1B[2 * i], wb1 = w1B[2 * i + 1];
#pragma unroll
                for (int b = 0; b < 4; b++) {
                    ulonglong2 hv = hq[b * 32 + i];
                    ffma2(acc[0][b], wa0, hv.x); ffma2(acc[0][b], wa1, hv.y);
                    ffma2(acc[1][b], wb0, hv.x); ffma2(acc[1][b], wb1, hv.y);
                }
            }
        }
        // ---- exchange: R1 k-reduce (partner w^8), R2 gate-gather (partner w^1) ----
        float s[2][4];
#pragma unroll
        for (int g = 0; g < 2; g++)
#pragma unroll
            for (int b = 0; b < 4; b++) s[g][b] = hadd2(acc[g][b]);
        float gate4[4];
        {
            float* scr1 = sm + OFF_H1 + qbuf * 2048;   // dead after L1 matvec reads
            float* scr2 = sm + OFF_H2 + pbuf * 2048;   // dead until post-mid-bar L2 bcast
            __syncthreads();                           // S0
#pragma unroll
            for (int j = 0; j < 2; j++) {              // send non-kept batches
                const int bl = (ks ^ 1) * 2 + j;
#pragma unroll
                for (int g = 0; g < 2; g++)
                    scr1[((((w & 7) * 2 + ks) * 2 + j) * 2 + g) * 32 + u] = s[g][bl];
            }
            __syncthreads();                           // S1
#pragma unroll
            for (int j = 0; j < 2; j++) {              // gather kept batches (full k)
                const int bl = ks * 2 + j;
#pragma unroll
                for (int g = 0; g < 2; g++)
                    s[g][bl] += scr1[((((w & 7) * 2 + (ks ^ 1)) * 2 + j) * 2 + g) * 32 + u];
            }
#pragma unroll
            for (int g = 0; g < 2; g++)                // R2: send my 2 gates of non-owned batch
                scr2[(((w >> 1) * 2 + gp) * 2 + g) * 32 + u] = s[g][ks * 2 + (gp ^ 1)];
            __syncthreads();                           // S2
#pragma unroll
            for (int g = 0; g < 2; g++) {
                gate4[2 * gp + g] = s[g][ks * 2 + gp];
                gate4[2 * (gp ^ 1) + g] = scr2[(((w >> 1) * 2 + (gp ^ 1)) * 2 + g) * 32 + u];
            }
        }
        // ---- layer-1 cell (1 owned batch) + cluster broadcast ----
        {
            float pi = fmaf(xv, wi0, gate4[0]) + bA0;
            float pf = fmaf(xv, wi1, gate4[1]) + bA1;
            float pg = fmaf(xv, wi2, gate4[2]) + bA2;
            float po = fmaf(xv, wi3, gate4[3]) + bA3;
            float ig = sigf(pi), fg = sigf(pf), gg = tanhf_fast(pg), og = sigf(po);
            float c = fmaf(fg, c1, ig * gg);
            c1 = c;
            float h = og * tanhf_fast(c);
            const uint32_t off = (uint32_t)((OFF_H1 + (pbuf * NB + owned) * 128 + gu) * 4);
#pragma unroll
            for (int r = 0; r < CLN; r++) st_cluster(peer[r] + off, h);
        }
        cluster_bar();   // h1[pbuf] complete cluster-wide

        // ========= layer 2 matvec: Wih2@h1[pbuf] + Whh2@h2[qbuf] =========
#pragma unroll
        for (int g = 0; g < 2; g++)
#pragma unroll
            for (int b = 0; b < 4; b++) acc[g][b] = 0ULL;
        {
            const ulonglong2* h1p =
                (const ulonglong2*)(sm + OFF_H1 + pbuf * 2048 + b0 * 128 + kbase);
            const ulonglong2* h2q =
                (const ulonglong2*)(sm + OFF_H2 + qbuf * 2048 + b0 * 128 + kbase);
#pragma unroll 2
            for (int i = 0; i < 16; ++i) {
                u64t p2a0 = w2A[2 * i], p2a1 = w2A[2 * i + 1];
                u64t p2b0 = w2B[2 * i], p2b1 = w2B[2 * i + 1];
                u64t p3a0 = w3A[2 * i], p3a1 = w3A[2 * i + 1];
                u64t p3b0 = w3B[2 * i], p3b1 = w3B[2 * i + 1];
#pragma unroll
                for (int b = 0; b < 4; b++) {
                    ulonglong2 pv = h1p[b * 32 + i];
                    ulonglong2 qv = h2q[b * 32 + i];
                    ffma2(acc[0][b], p2a0, pv.x); ffma2(acc[0][b], p2a1, pv.y);
                    ffma2(acc[1][b], p2b0, pv.x); ffma2(acc[1][b], p2b1, pv.y);
                    ffma2(acc[0][b], p3a0, qv.x); ffma2(acc[0][b], p3a1, qv.y);
                    ffma2(acc[1][b], p3b0, qv.x); ffma2(acc[1][b], p3b1, qv.y);
                }
            }
        }
        // ---- exchange (scratch: h2[qbuf] R1, h1[qbuf] R2 — both dead) ----
#pragma unroll
        for (int g = 0; g < 2; g++)
#pragma unroll
            for (int b = 0; b < 4; b++) s[g][b] = hadd2(acc[g][b]);
        {
            float* scr1 = sm + OFF_H2 + qbuf * 2048;
            float* scr2 = sm + OFF_H1 + qbuf * 2048;
            __syncthreads();                           // S0'
#pragma unroll
            for (int j = 0; j < 2; j++) {
                const int bl = (ks ^ 1) * 2 + j;
#pragma unroll
                for (int g = 0; g < 2; g++)
                    scr1[((((w & 7) * 2 + ks) * 2 + j) * 2 + g) * 32 + u] = s[g][bl];
            }
            __syncthreads();                           // S1'
#pragma unroll
            for (int j = 0; j < 2; j++) {
                const int bl = ks * 2 + j;
#pragma unroll
                for (int g = 0; g < 2; g++)
                    s[g][bl] += scr1[((((w & 7) * 2 + (ks ^ 1)) * 2 + j) * 2 + g) * 32 + u];
            }
#pragma unroll
            for (int g = 0; g < 2; g++)
                scr2[(((w >> 1) * 2 + gp) * 2 + g) * 32 + u] = s[g][ks * 2 + (gp ^ 1)];
            __syncthreads();                           // S2'
#pragma unroll
            for (int g = 0; g < 2; g++) {
                gate4[2 * gp + g] = s[g][ks * 2 + gp];
                gate4[2 * (gp ^ 1) + g] = scr2[(((w >> 1) * 2 + (gp ^ 1)) * 2 + g) * 32 + u];
            }
        }
        // ---- layer-2 cell + broadcast ----
        {
            float pi = gate4[0] + bB0;
            float pf = gate4[1] + bB1;
            float pg = gate4[2] + bB2;
            float po = gate4[3] + bB3;
            float ig = sigf(pi), fg = sigf(pf), gg = tanhf_fast(pg), og = sigf(po);
            float c = fmaf(fg, c2, ig * gg);
            c2 = c;
            float h = og * tanhf_fast(c);
            const uint32_t off = (uint32_t)((OFF_H2 + (pbuf * NB + owned) * 128 + gu) * 4);
#pragma unroll
            for (int r = 0; r < CLN; r++) st_cluster(peer[r] + off, h);
        }
        cluster_bar();   // h2[pbuf] complete cluster-wide

        // ---- output head: each warp emits its owned batch ----
        {
            const float* hp = sm + OFF_H2 + pbuf * 2048 + owned * 128;
            float d = hp[u] * wl0 + hp[u + 32] * wl1 + hp[u + 64] * wl2 + hp[u + 96] * wl3;
#pragma unroll
            for (int m = 16; m >= 1; m >>= 1)
                d += __shfl_xor_sync(0xffffffffu, d, m);
            if (u == 0) out[xrow + t] = d + blin;
        }
    }
}

extern "C" void kernel_launch(void* const* d_in, const int* in_sizes, int n_in,
                              void* d_out, int out_size)
{
    (void)in_sizes; (void)n_in; (void)out_size;
    cudaFuncSetAttribute(lstm_persistent_kernel,
                         cudaFuncAttributeMaxDynamicSharedMemorySize, SMEM_BYTES);
    lstm_persistent_kernel<<<(BBZ / NB) * CLN, NTHREADS, SMEM_BYTES>>>(
        (const float*)d_in[0], (const float*)d_in[1], (const float*)d_in[2],
        (const float*)d_in[3], (const float*)d_in[4], (const float*)d_in[5],
        (const float*)d_in[6], (const float*)d_in[7], (const float*)d_in[8],
        (const float*)d_in[9], (const float*)d_in[10], (float*)d_out);
}